// round 8
// baseline (speedup 1.0000x reference)
#include <cuda_runtime.h>
#include <cstdint>

#define BATCH 8
#define IN_F 4096
#define OUT_F 12288
#define GS 128
#define NG 32
#define OPW 4            // outputs per warp
#define WPB 4            // warps per CTA
#define TPB (WPB * 32)
#define OPC (WPB * OPW)  // 16 outputs per CTA
#define NSTG 3           // x smem stages

typedef unsigned long long u64;

__device__ float g_sx[BATCH * NG];

__device__ __forceinline__ u64 pack2(float lo, float hi) {
    u64 r; asm("mov.b64 %0, {%1, %2};" : "=l"(r) : "f"(lo), "f"(hi)); return r;
}
__device__ __forceinline__ void unpack2(u64 v, float& lo, float& hi) {
    asm("mov.b64 {%0, %1}, %2;" : "=f"(lo), "=f"(hi) : "l"(v));
}
__device__ __forceinline__ u64 fma2(u64 a, u64 b, u64 c) {
    u64 d; asm("fma.rn.f32x2 %0, %1, %2, %3;" : "=l"(d) : "l"(a), "l"(b), "l"(c)); return d;
}
__device__ __forceinline__ u64 mul2(u64 a, u64 b) {
    u64 d; asm("mul.rn.f32x2 %0, %1, %2;" : "=l"(d) : "l"(a), "l"(b)); return d;
}
// weights: streaming, evict-first (protect x in L1)
__device__ __forceinline__ int4 ldg_cs(const int* p) {
    int4 v;
    asm("ld.global.cs.v4.u32 {%0,%1,%2,%3}, [%4];"
        : "=r"(v.x), "=r"(v.y), "=r"(v.z), "=r"(v.w) : "l"(p));
    return v;
}
// x fill: cp.async with L1 caching (x stays L1-resident; no register transit)
__device__ __forceinline__ void cp_ca16(uint32_t dst, const void* src) {
    asm volatile("cp.async.ca.shared.global [%0], [%1], 16;" :: "r"(dst), "l"(src));
}

// ---- prekernel: Sx[b][g] = sum of x over group g ----
__global__ void prep_kernel(const float* __restrict__ x) {
    const int gt   = blockIdx.x * blockDim.x + threadIdx.x;
    const int w    = gt >> 5;
    const int lane = gt & 31;
    const int base = (w >> 5) * IN_F + (w & 31) * GS + lane * 4;
    float4 v = __ldg((const float4*)(x + base));
    float s = (v.x + v.y) + (v.z + v.w);
    #pragma unroll
    for (int off = 16; off > 0; off >>= 1)
        s += __shfl_xor_sync(0xffffffffu, s, off);
    if (lane == 0) g_sx[w] = s;
}

// ---- main kernel ----
__global__ void __launch_bounds__(TPB, 4)
w4a32_main(const float* __restrict__ x, const int* __restrict__ qw,
           const float* __restrict__ sc, const float* __restrict__ zr,
           float* __restrict__ out)
{
    __shared__ __align__(16) float xs[NSTG][BATCH][GS];   // 12 KB x stages
    __shared__ float bounce[WPB][OPW * BATCH];

    const int tid    = threadIdx.x;
    const int warp   = tid >> 5;
    const int lane   = tid & 31;
    const int cta_n0 = blockIdx.x * OPC;
    const int n0     = cta_n0 + warp * OPW;
    const int klo    = lane * 4;

    const int* qbase = qw + (long)n0 * IN_F + klo;

    // stage x group g into xs[st] (256 x 16B chunks over 128 threads)
    auto xissue = [&](int g, int st) {
        #pragma unroll
        for (int i = 0; i < 2; ++i) {
            const int idx = tid + i * TPB;           // 0..255
            const int b = idx >> 5, j = (idx & 31) << 2;
            cp_ca16((uint32_t)__cvta_generic_to_shared(&xs[st][b][j]),
                    x + b * IN_F + g * GS + j);
        }
        asm volatile("cp.async.commit_group;");
    };

    xissue(0, 0);
    xissue(1, 1);

    // weights + scales: register pipeline depth 2 (R6-proven)
    int4 qbuf[2][OPW];
    float4 svbuf[2];
    #pragma unroll
    for (int s = 0; s < 2; ++s) {
        #pragma unroll
        for (int o = 0; o < OPW; ++o)
            qbuf[s][o] = ldg_cs(qbase + s * GS + o * IN_F);
        svbuf[s] = __ldg((const float4*)(sc + s * OUT_F + n0));
    }

    u64 acc[OPW][BATCH];
    #pragma unroll
    for (int o = 0; o < OPW; ++o)
        #pragma unroll
        for (int b = 0; b < BATCH; ++b) acc[o][b] = 0ull;

    int st = 0;
    #pragma unroll 1
    for (int g = 0; g < NG; ++g) {
        const int cur = g & 1;

        if (g < NG - 2) asm volatile("cp.async.wait_group 1;");
        else            asm volatile("cp.async.wait_group 0;");
        __syncthreads();   // xs[st] readable; everyone done with stage st+2 (mod 3)

        // refill the stage consumed 2 iterations ago with group g+2
        if (g + 2 < NG) {
            int stw = st + 2; if (stw >= NSTG) stw -= NSTG;
            xissue(g + 2, stw);
        }

        // convert current weight group: qs[o] = (s*q0,s*q1),(s*q2,s*q3)
        u64 qs[OPW][2];
        {
            const float4 sv = svbuf[cur];
            const float sa[OPW] = {sv.x, sv.y, sv.z, sv.w};
            #pragma unroll
            for (int o = 0; o < OPW; ++o) {
                const int4 q = qbuf[cur][o];
                u64 s2 = pack2(sa[o], sa[o]);
                qs[o][0] = mul2(pack2((float)q.x, (float)q.y), s2);
                qs[o][1] = mul2(pack2((float)q.z, (float)q.w), s2);
            }
        }
        // prefetch weights + scales for g+2 into the buffer just consumed
        {
            const int gn2 = (g + 2) & (NG - 1);
            #pragma unroll
            for (int o = 0; o < OPW; ++o)
                qbuf[cur][o] = ldg_cs(qbase + gn2 * GS + o * IN_F);
            svbuf[cur] = __ldg((const float4*)(sc + gn2 * OUT_F + n0));
        }

        // math: x pairs from the shared stage (smem crossbar, not L1tex)
        #pragma unroll
        for (int b = 0; b < BATCH; ++b) {
            ulonglong2 xv = *(const ulonglong2*)&xs[st][b][klo];
            #pragma unroll
            for (int o = 0; o < OPW; ++o) {
                acc[o][b] = fma2(xv.x, qs[o][0], acc[o][b]);
                acc[o][b] = fma2(xv.y, qs[o][1], acc[o][b]);
            }
        }

        if (++st == NSTG) st = 0;
    }

    // ---- pair-halves add, butterfly across 32 lanes ----
    float r[OPW][BATCH];
    #pragma unroll
    for (int o = 0; o < OPW; ++o)
        #pragma unroll
        for (int b = 0; b < BATCH; ++b) {
            float lo, hi; unpack2(acc[o][b], lo, hi);
            r[o][b] = lo + hi;
        }
    #pragma unroll
    for (int off = 16; off > 0; off >>= 1)
        #pragma unroll
        for (int o = 0; o < OPW; ++o)
            #pragma unroll
            for (int b = 0; b < BATCH; ++b)
                r[o][b] += __shfl_xor_sync(0xffffffffu, r[o][b], off);

    if (lane == 0) {
        #pragma unroll
        for (int o = 0; o < OPW; ++o)
            #pragma unroll
            for (int b = 0; b < BATCH; ++b)
                bounce[warp][o * BATCH + b] = r[o][b];
    }
    __syncwarp();

    // 32 results per warp, one per lane; fold in zero/offset term
    const int o = lane >> 3, b = lane & 7;
    const int n = n0 + o;
    float offt = 0.f;
    #pragma unroll
    for (int g2 = 0; g2 < NG; ++g2) {
        float s = __ldg(sc + g2 * OUT_F + n);
        float z = __ldg(zr + g2 * OUT_F + n);
        offt = fmaf(z - 8.f * s, g_sx[b * NG + g2], offt);
    }
    out[b * OUT_F + n] = bounce[warp][lane] + offt;
}

extern "C" void kernel_launch(void* const* d_in, const int* in_sizes, int n_in,
                              void* d_out, int out_size) {
    const float* x  = (const float*)d_in[0];
    const int*   qw = (const int*)d_in[1];
    const float* sc = (const float*)d_in[2];
    const float* zr = (const float*)d_in[3];
    float* out = (float*)d_out;

    prep_kernel<<<32, 256>>>(x);
    w4a32_main<<<OUT_F / OPC, TPB>>>(x, qw, sc, zr, out);   // 768 x 128
}

// round 9
// speedup vs baseline: 1.4839x; 1.4839x over previous
#include <cuda_runtime.h>
#include <cuda_fp16.h>
#include <cstdint>

#define BATCH 8
#define IN_F 4096
#define OUT_F 12288
#define GS 128
#define NG 32
#define OPW 4          // outputs per warp
#define TPB 32         // one warp per CTA (no intra-CTA sync anywhere)

typedef unsigned long long u64;

__device__ float  g_sx[BATCH * NG];      // per-batch per-group sums of x (fp32, exact)
__device__ __half g_xh[BATCH * IN_F];    // x converted to fp16 (64 KB, L1-resident)

__device__ __forceinline__ u64 pack2(float lo, float hi) {
    u64 r; asm("mov.b64 %0, {%1, %2};" : "=l"(r) : "f"(lo), "f"(hi)); return r;
}
__device__ __forceinline__ void unpack2(u64 v, float& lo, float& hi) {
    asm("mov.b64 {%0, %1}, %2;" : "=f"(lo), "=f"(hi) : "l"(v));
}
__device__ __forceinline__ u64 fma2(u64 a, u64 b, u64 c) {
    u64 d; asm("fma.rn.f32x2 %0, %1, %2, %3;" : "=l"(d) : "l"(a), "l"(b), "l"(c)); return d;
}
__device__ __forceinline__ u64 mul2(u64 a, u64 b) {
    u64 d; asm("mul.rn.f32x2 %0, %1, %2;" : "=l"(d) : "l"(a), "l"(b)); return d;
}
// weights: streaming, evict-first (protect x in L1)
__device__ __forceinline__ int4 ldg_cs(const int* p) {
    int4 v;
    asm("ld.global.cs.v4.u32 {%0,%1,%2,%3}, [%4];"
        : "=r"(v.x), "=r"(v.y), "=r"(v.z), "=r"(v.w) : "l"(p));
    return v;
}
// x (fp16): 8B per lane, keep resident in L1
__device__ __forceinline__ uint2 ldg_xh(const __half* p) {
    uint2 v;
    asm("ld.global.nc.L1::evict_last.v2.u32 {%0,%1}, [%2];"
        : "=r"(v.x), "=r"(v.y) : "l"(p));
    return v;
}

// ---- prekernel: x -> fp16, plus Sx[b][g] group sums (warp per (b,g)) ----
__global__ void prep_kernel(const float* __restrict__ x) {
    const int gt   = blockIdx.x * blockDim.x + threadIdx.x;
    const int w    = gt >> 5;            // 0..255 = b*32 + g
    const int lane = gt & 31;
    const int base = (w >> 5) * IN_F + (w & 31) * GS + lane * 4;

    float4 v = __ldg((const float4*)(x + base));

    __half2 h01 = __floats2half2_rn(v.x, v.y);
    __half2 h23 = __floats2half2_rn(v.z, v.w);
    uint2 p;
    p.x = *(const unsigned*)&h01;
    p.y = *(const unsigned*)&h23;
    *(uint2*)(g_xh + base) = p;

    float s = (v.x + v.y) + (v.z + v.w);
    #pragma unroll
    for (int off = 16; off > 0; off >>= 1)
        s += __shfl_xor_sync(0xffffffffu, s, off);
    if (lane == 0) g_sx[w] = s;
}

// ---- main kernel: one warp per 4 outputs; barrier-free mainloop ----
__global__ void __launch_bounds__(TPB, 13)
w4a32_main(const int* __restrict__ qw,
           const float* __restrict__ sc, const float* __restrict__ zr,
           float* __restrict__ out)
{
    __shared__ float bounce[OPW * BATCH];

    const int lane = threadIdx.x;
    const int n0   = blockIdx.x * OPW;
    const int klo  = lane * 4;

    const int* qbase = qw + (long)n0 * IN_F + klo;

    // weights + scales: register pipeline depth 2
    int4 qbuf[2][OPW];
    float4 svbuf[2];
    #pragma unroll
    for (int s = 0; s < 2; ++s) {
        #pragma unroll
        for (int o = 0; o < OPW; ++o)
            qbuf[s][o] = ldg_cs(qbase + s * GS + o * IN_F);
        svbuf[s] = __ldg((const float4*)(sc + s * OUT_F + n0));
    }

    // x (fp16 pairs): register pipeline depth 1
    uint2 xcur[BATCH];
    #pragma unroll
    for (int b = 0; b < BATCH; ++b)
        xcur[b] = ldg_xh(g_xh + b * IN_F + klo);

    u64 acc[OPW][BATCH];
    #pragma unroll
    for (int o = 0; o < OPW; ++o)
        #pragma unroll
        for (int b = 0; b < BATCH; ++b) acc[o][b] = 0ull;

    #pragma unroll 2
    for (int g = 0; g < NG; ++g) {
        const int cur = g & 1;

        // convert current weight group: qs[o] = (s*q0,s*q1),(s*q2,s*q3)
        u64 qs[OPW][2];
        {
            const float4 sv = svbuf[cur];
            const float sa[OPW] = {sv.x, sv.y, sv.z, sv.w};
            #pragma unroll
            for (int o = 0; o < OPW; ++o) {
                const int4 q = qbuf[cur][o];
                u64 s2 = pack2(sa[o], sa[o]);
                qs[o][0] = mul2(pack2((float)q.x, (float)q.y), s2);
                qs[o][1] = mul2(pack2((float)q.z, (float)q.w), s2);
            }
        }

        // prefetch weights + scales for g+2 into the buffer just consumed
        {
            const int gn2 = (g + 2) & (NG - 1);
            #pragma unroll
            for (int o = 0; o < OPW; ++o)
                qbuf[cur][o] = ldg_cs(qbase + gn2 * GS + o * IN_F);
            svbuf[cur] = __ldg((const float4*)(sc + gn2 * OUT_F + n0));
        }

        // math for group g; per-batch, prefetch x for g+1 right after consuming
        const __half* xg1 = g_xh + ((g + 1) & (NG - 1)) * GS + klo;
        #pragma unroll
        for (int b = 0; b < BATCH; ++b) {
            const uint2 xv = xcur[b];
            xcur[b] = ldg_xh(xg1 + b * IN_F);       // half-iteration-ahead prefetch

            // half4 -> two fp32 pairs
            float2 f01 = __half22float2(*(const __half2*)&xv.x);
            float2 f23 = __half22float2(*(const __half2*)&xv.y);
            u64 x01 = pack2(f01.x, f01.y);
            u64 x23 = pack2(f23.x, f23.y);

            #pragma unroll
            for (int o = 0; o < OPW; ++o) {
                acc[o][b] = fma2(x01, qs[o][0], acc[o][b]);
                acc[o][b] = fma2(x23, qs[o][1], acc[o][b]);
            }
        }
    }

    // ---- pair-halves add, butterfly across 32 lanes ----
    float r[OPW][BATCH];
    #pragma unroll
    for (int o = 0; o < OPW; ++o)
        #pragma unroll
        for (int b = 0; b < BATCH; ++b) {
            float lo, hi; unpack2(acc[o][b], lo, hi);
            r[o][b] = lo + hi;
        }
    #pragma unroll
    for (int off = 16; off > 0; off >>= 1)
        #pragma unroll
        for (int o = 0; o < OPW; ++o)
            #pragma unroll
            for (int b = 0; b < BATCH; ++b)
                r[o][b] += __shfl_xor_sync(0xffffffffu, r[o][b], off);

    if (lane == 0) {
        #pragma unroll
        for (int o = 0; o < OPW; ++o)
            #pragma unroll
            for (int b = 0; b < BATCH; ++b)
                bounce[o * BATCH + b] = r[o][b];
    }
    __syncwarp();

    // 32 results, one per lane; fold in zero/offset term
    const int o = lane >> 3, b = lane & 7;
    const int n = n0 + o;
    float offt = 0.f;
    #pragma unroll
    for (int g2 = 0; g2 < NG; ++g2) {
        float s = __ldg(sc + g2 * OUT_F + n);
        float z = __ldg(zr + g2 * OUT_F + n);
        offt = fmaf(z - 8.f * s, g_sx[b * NG + g2], offt);
    }
    out[b * OUT_F + n] = bounce[lane] + offt;
}

extern "C" void kernel_launch(void* const* d_in, const int* in_sizes, int n_in,
                              void* d_out, int out_size) {
    const float* x  = (const float*)d_in[0];
    const int*   qw = (const int*)d_in[1];
    const float* sc = (const float*)d_in[2];
    const float* zr = (const float*)d_in[3];
    float* out = (float*)d_out;

    prep_kernel<<<32, 256>>>(x);
    w4a32_main<<<OUT_F / OPW, TPB>>>(qw, sc, zr, out);   // 3072 x 32
}

// round 10
// speedup vs baseline: 1.9418x; 1.3086x over previous
#include <cuda_runtime.h>
#include <cstdint>

#define BATCH 8
#define IN_F 4096
#define OUT_F 12288
#define GS 128
#define NG 32
#define OPW 4          // outputs per tile
#define TILES 2        // tiles per CTA (persistent)
#define TPB 32         // one warp per CTA (no intra-CTA sync anywhere)

typedef unsigned long long u64;

__device__ float g_sx[BATCH * NG];      // per-batch per-group sums of x

__device__ __forceinline__ u64 pack2(float lo, float hi) {
    u64 r; asm("mov.b64 %0, {%1, %2};" : "=l"(r) : "f"(lo), "f"(hi)); return r;
}
__device__ __forceinline__ void unpack2(u64 v, float& lo, float& hi) {
    asm("mov.b64 {%0, %1}, %2;" : "=f"(lo), "=f"(hi) : "l"(v));
}
__device__ __forceinline__ u64 fma2(u64 a, u64 b, u64 c) {
    u64 d; asm("fma.rn.f32x2 %0, %1, %2, %3;" : "=l"(d) : "l"(a), "l"(b), "l"(c)); return d;
}
__device__ __forceinline__ u64 mul2(u64 a, u64 b) {
    u64 d; asm("mul.rn.f32x2 %0, %1, %2;" : "=l"(d) : "l"(a), "l"(b)); return d;
}
// weights: streaming, evict-first (protect x in L1)
__device__ __forceinline__ int4 ldg_cs(const int* p) {
    int4 v;
    asm("ld.global.cs.v4.u32 {%0,%1,%2,%3}, [%4];"
        : "=r"(v.x), "=r"(v.y), "=r"(v.z), "=r"(v.w) : "l"(p));
    return v;
}
// x: pairs along k, keep resident in L1
__device__ __forceinline__ ulonglong2 ldg_x2(const float* p) {
    ulonglong2 v;
    asm("ld.global.nc.L1::evict_last.v2.u64 {%0,%1}, [%2];"
        : "=l"(v.x), "=l"(v.y) : "l"(p));
    return v;
}

// ---- prekernel: Sx[b][g] = sum of x over group g (warp per (b,g)) ----
__global__ void prep_kernel(const float* __restrict__ x) {
    const int gt   = blockIdx.x * blockDim.x + threadIdx.x;
    const int w    = gt >> 5;            // 0..255 = b*32 + g
    const int lane = gt & 31;
    const int base = (w >> 5) * IN_F + (w & 31) * GS + lane * 4;
    float4 v = __ldg((const float4*)(x + base));
    float s = (v.x + v.y) + (v.z + v.w);
    #pragma unroll
    for (int off = 16; off > 0; off >>= 1)
        s += __shfl_xor_sync(0xffffffffu, s, off);
    if (lane == 0) g_sx[w] = s;
}

// ---- main kernel: persistent warp, 2 sequential tiles of 4 outputs ----
__global__ void __launch_bounds__(TPB, 12)
w4a32_main(const float* __restrict__ x, const int* __restrict__ qw,
           const float* __restrict__ sc, const float* __restrict__ zr,
           float* __restrict__ out)
{
    __shared__ float bounce[OPW * BATCH];

    const int lane = threadIdx.x;
    const int klo  = lane * 4;

    #pragma unroll 1
    for (int t = 0; t < TILES; ++t) {
        const int n0 = (blockIdx.x * TILES + t) * OPW;
        const int* qbase = qw + (long)n0 * IN_F + klo;

        // weights + scales: register pipeline depth 2
        int4 qbuf[2][OPW];
        float4 svbuf[2];
        #pragma unroll
        for (int s = 0; s < 2; ++s) {
            #pragma unroll
            for (int o = 0; o < OPW; ++o)
                qbuf[s][o] = ldg_cs(qbase + s * GS + o * IN_F);
            svbuf[s] = __ldg((const float4*)(sc + s * OUT_F + n0));
        }

        // x: register pipeline depth 1 (pairs along k)
        ulonglong2 xcur[BATCH];
        #pragma unroll
        for (int b = 0; b < BATCH; ++b)
            xcur[b] = ldg_x2(x + b * IN_F + klo);

        u64 acc[OPW][BATCH];
        #pragma unroll
        for (int o = 0; o < OPW; ++o)
            #pragma unroll
            for (int b = 0; b < BATCH; ++b) acc[o][b] = 0ull;

        #pragma unroll 2
        for (int g = 0; g < NG; ++g) {
            const int cur = g & 1;

            // convert current group: qs[o] = (s*q0,s*q1),(s*q2,s*q3)
            u64 qs[OPW][2];
            {
                const float4 sv = svbuf[cur];
                const float sa[OPW] = {sv.x, sv.y, sv.z, sv.w};
                #pragma unroll
                for (int o = 0; o < OPW; ++o) {
                    const int4 q = qbuf[cur][o];
                    u64 s2 = pack2(sa[o], sa[o]);
                    qs[o][0] = mul2(pack2((float)q.x, (float)q.y), s2);
                    qs[o][1] = mul2(pack2((float)q.z, (float)q.w), s2);
                }
            }

            // prefetch weights + scales for g+2 into the buffer just consumed
            {
                const int gn2 = (g + 2) & (NG - 1);
                #pragma unroll
                for (int o = 0; o < OPW; ++o)
                    qbuf[cur][o] = ldg_cs(qbase + gn2 * GS + o * IN_F);
                svbuf[cur] = __ldg((const float4*)(sc + gn2 * OUT_F + n0));
            }

            // math for group g; per-batch, reload x for g+1 right after consuming
            const float* xg1 = x + ((g + 1) & (NG - 1)) * GS + klo;
            #pragma unroll
            for (int b = 0; b < BATCH; ++b) {
                const ulonglong2 xv = xcur[b];
                xcur[b] = ldg_x2(xg1 + b * IN_F);   // half-iteration-ahead prefetch
                #pragma unroll
                for (int o = 0; o < OPW; ++o) {
                    acc[o][b] = fma2(xv.x, qs[o][0], acc[o][b]);
                    acc[o][b] = fma2(xv.y, qs[o][1], acc[o][b]);
                }
            }
        }

        // ---- pair-halves add, butterfly across 32 lanes ----
        float r[OPW][BATCH];
        #pragma unroll
        for (int o = 0; o < OPW; ++o)
            #pragma unroll
            for (int b = 0; b < BATCH; ++b) {
                float lo, hi; unpack2(acc[o][b], lo, hi);
                r[o][b] = lo + hi;
            }
        #pragma unroll
        for (int off = 16; off > 0; off >>= 1)
            #pragma unroll
            for (int o = 0; o < OPW; ++o)
                #pragma unroll
                for (int b = 0; b < BATCH; ++b)
                    r[o][b] += __shfl_xor_sync(0xffffffffu, r[o][b], off);

        if (lane == 0) {
            #pragma unroll
            for (int o = 0; o < OPW; ++o)
                #pragma unroll
                for (int b = 0; b < BATCH; ++b)
                    bounce[o * BATCH + b] = r[o][b];
        }
        __syncwarp();

        // 32 results, one per lane; fold in zero/offset term
        const int o = lane >> 3, b = lane & 7;
        const int n = n0 + o;
        float offt = 0.f;
        #pragma unroll
        for (int g2 = 0; g2 < NG; ++g2) {
            float s = __ldg(sc + g2 * OUT_F + n);
            float z = __ldg(zr + g2 * OUT_F + n);
            offt = fmaf(z - 8.f * s, g_sx[b * NG + g2], offt);
        }
        out[b * OUT_F + n] = bounce[lane] + offt;
        __syncwarp();    // bounce reused next tile
    }
}

extern "C" void kernel_launch(void* const* d_in, const int* in_sizes, int n_in,
                              void* d_out, int out_size) {
    const float* x  = (const float*)d_in[0];
    const int*   qw = (const int*)d_in[1];
    const float* sc = (const float*)d_in[2];
    const float* zr = (const float*)d_in[3];
    float* out = (float*)d_out;

    prep_kernel<<<32, 256>>>(x);
    w4a32_main<<<OUT_F / (OPW * TILES), TPB>>>(x, qw, sc, zr, out);  // 1536 x 32
}

// round 11
// speedup vs baseline: 1.9593x; 1.0090x over previous
#include <cuda_runtime.h>
#include <cuda_fp16.h>
#include <cstdint>

#define BATCH 8
#define IN_F 4096
#define OUT_F 12288
#define GS 128
#define NG 32
#define OPW 4          // outputs per warp
#define TPB 32         // one warp per CTA (no intra-CTA sync anywhere)

typedef unsigned long long u64;

__device__ float  g_sx[BATCH * NG];      // per-batch per-group sums of x (fp32, exact)
__device__ __half g_xh[BATCH * IN_F];    // x converted to fp16 (64 KB, L1-resident)

__device__ __forceinline__ u64 pack2(float lo, float hi) {
    u64 r; asm("mov.b64 %0, {%1, %2};" : "=l"(r) : "f"(lo), "f"(hi)); return r;
}
__device__ __forceinline__ void unpack2(u64 v, float& lo, float& hi) {
    asm("mov.b64 {%0, %1}, %2;" : "=f"(lo), "=f"(hi) : "l"(v));
}
__device__ __forceinline__ u64 fma2(u64 a, u64 b, u64 c) {
    u64 d; asm("fma.rn.f32x2 %0, %1, %2, %3;" : "=l"(d) : "l"(a), "l"(b), "l"(c)); return d;
}
__device__ __forceinline__ u64 mul2(u64 a, u64 b) {
    u64 d; asm("mul.rn.f32x2 %0, %1, %2;" : "=l"(d) : "l"(a), "l"(b)); return d;
}
// weights: streaming, evict-first (protect x in L1)
__device__ __forceinline__ int4 ldg_cs(const int* p) {
    int4 v;
    asm("ld.global.cs.v4.u32 {%0,%1,%2,%3}, [%4];"
        : "=r"(v.x), "=r"(v.y), "=r"(v.z), "=r"(v.w) : "l"(p));
    return v;
}
// x (fp16): 8B per lane, keep resident in L1
__device__ __forceinline__ uint2 ldg_xh(const __half* p) {
    uint2 v;
    asm("ld.global.nc.L1::evict_last.v2.u32 {%0,%1}, [%2];"
        : "=r"(v.x), "=r"(v.y) : "l"(p));
    return v;
}

// ---- prekernel: x -> fp16, plus Sx[b][g] group sums (warp per (b,g)) ----
__global__ void prep_kernel(const float* __restrict__ x) {
    const int gt   = blockIdx.x * blockDim.x + threadIdx.x;
    const int w    = gt >> 5;            // 0..255 = b*32 + g
    const int lane = gt & 31;
    const int base = (w >> 5) * IN_F + (w & 31) * GS + lane * 4;

    float4 v = __ldg((const float4*)(x + base));

    __half2 h01 = __floats2half2_rn(v.x, v.y);
    __half2 h23 = __floats2half2_rn(v.z, v.w);
    uint2 p;
    p.x = *(const unsigned*)&h01;
    p.y = *(const unsigned*)&h23;
    *(uint2*)(g_xh + base) = p;

    float s = (v.x + v.y) + (v.z + v.w);
    #pragma unroll
    for (int off = 16; off > 0; off >>= 1)
        s += __shfl_xor_sync(0xffffffffu, s, off);
    if (lane == 0) g_sx[w] = s;
}

// ---- main kernel: one warp per 4 outputs; barrier-free mainloop ----
// launch_bounds(32,12): allow up to ~170 regs — do NOT force the 128-reg spill.
__global__ void __launch_bounds__(TPB, 12)
w4a32_main(const int* __restrict__ qw,
           const float* __restrict__ sc, const float* __restrict__ zr,
           float* __restrict__ out)
{
    __shared__ float bounce[OPW * BATCH];

    const int lane = threadIdx.x;
    const int n0   = blockIdx.x * OPW;
    const int klo  = lane * 4;

    const int* qbase = qw + (long)n0 * IN_F + klo;

    // weights + scales: register pipeline depth 2
    int4 qbuf[2][OPW];
    float4 svbuf[2];
    #pragma unroll
    for (int s = 0; s < 2; ++s) {
        #pragma unroll
        for (int o = 0; o < OPW; ++o)
            qbuf[s][o] = ldg_cs(qbase + s * GS + o * IN_F);
        svbuf[s] = __ldg((const float4*)(sc + s * OUT_F + n0));
    }

    // x (fp16 pairs): register pipeline depth 1
    uint2 xcur[BATCH];
    #pragma unroll
    for (int b = 0; b < BATCH; ++b)
        xcur[b] = ldg_xh(g_xh + b * IN_F + klo);

    u64 acc[OPW][BATCH];
    #pragma unroll
    for (int o = 0; o < OPW; ++o)
        #pragma unroll
        for (int b = 0; b < BATCH; ++b) acc[o][b] = 0ull;

    #pragma unroll 2
    for (int g = 0; g < NG; ++g) {
        const int cur = g & 1;

        // convert current weight group: qs[o] = (s*q0,s*q1),(s*q2,s*q3)
        u64 qs[OPW][2];
        {
            const float4 sv = svbuf[cur];
            const float sa[OPW] = {sv.x, sv.y, sv.z, sv.w};
            #pragma unroll
            for (int o = 0; o < OPW; ++o) {
                const int4 q = qbuf[cur][o];
                u64 s2 = pack2(sa[o], sa[o]);
                qs[o][0] = mul2(pack2((float)q.x, (float)q.y), s2);
                qs[o][1] = mul2(pack2((float)q.z, (float)q.w), s2);
            }
        }

        // prefetch weights + scales for g+2 into the buffer just consumed
        {
            const int gn2 = (g + 2) & (NG - 1);
            #pragma unroll
            for (int o = 0; o < OPW; ++o)
                qbuf[cur][o] = ldg_cs(qbase + gn2 * GS + o * IN_F);
            svbuf[cur] = __ldg((const float4*)(sc + gn2 * OUT_F + n0));
        }

        // math for group g; per-batch, prefetch x for g+1 right after consuming
        const __half* xg1 = g_xh + ((g + 1) & (NG - 1)) * GS + klo;
        #pragma unroll
        for (int b = 0; b < BATCH; ++b) {
            const uint2 xv = xcur[b];
            xcur[b] = ldg_xh(xg1 + b * IN_F);       // half-iteration-ahead prefetch

            // half4 -> two fp32 pairs
            float2 f01 = __half22float2(*(const __half2*)&xv.x);
            float2 f23 = __half22float2(*(const __half2*)&xv.y);
            u64 x01 = pack2(f01.x, f01.y);
            u64 x23 = pack2(f23.x, f23.y);

            #pragma unroll
            for (int o = 0; o < OPW; ++o) {
                acc[o][b] = fma2(x01, qs[o][0], acc[o][b]);
                acc[o][b] = fma2(x23, qs[o][1], acc[o][b]);
            }
        }
    }

    // ---- pair-halves add, butterfly across 32 lanes ----
    float r[OPW][BATCH];
    #pragma unroll
    for (int o = 0; o < OPW; ++o)
        #pragma unroll
        for (int b = 0; b < BATCH; ++b) {
            float lo, hi; unpack2(acc[o][b], lo, hi);
            r[o][b] = lo + hi;
        }
    #pragma unroll
    for (int off = 16; off > 0; off >>= 1)
        #pragma unroll
        for (int o = 0; o < OPW; ++o)
            #pragma unroll
            for (int b = 0; b < BATCH; ++b)
                r[o][b] += __shfl_xor_sync(0xffffffffu, r[o][b], off);

    if (lane == 0) {
        #pragma unroll
        for (int o = 0; o < OPW; ++o)
            #pragma unroll
            for (int b = 0; b < BATCH; ++b)
                bounce[o * BATCH + b] = r[o][b];
    }
    __syncwarp();

    // 32 results, one per lane; fold in zero/offset term
    const int o = lane >> 3, b = lane & 7;
    const int n = n0 + o;
    float offt = 0.f;
    #pragma unroll
    for (int g2 = 0; g2 < NG; ++g2) {
        float s = __ldg(sc + g2 * OUT_F + n);
        float z = __ldg(zr + g2 * OUT_F + n);
        offt = fmaf(z - 8.f * s, g_sx[b * NG + g2], offt);
    }
    out[b * OUT_F + n] = bounce[lane] + offt;
}

extern "C" void kernel_launch(void* const* d_in, const int* in_sizes, int n_in,
                              void* d_out, int out_size) {
    const float* x  = (const float*)d_in[0];
    const int*   qw = (const int*)d_in[1];
    const float* sc = (const float*)d_in[2];
    const float* zr = (const float*)d_in[3];
    float* out = (float*)d_out;

    prep_kernel<<<32, 256>>>(x);
    w4a32_main<<<OUT_F / OPW, TPB>>>(qw, sc, zr, out);   // 3072 x 32
}